// round 1
// baseline (speedup 1.0000x reference)
#include <cuda_runtime.h>
#include <cstdint>
#include <cstddef>

// ---------------- problem constants ----------------
#define BATCH   2
#define NRES    2048
#define NBLADE  16
#define TILE_N  16      // n rows per block
#define MTILE   512     // m rows per block (2 per thread)
#define THREADS 256

typedef unsigned long long ull;

// ---------------- compile-time GP basis table (REV folded in) ----------------
constexpr int cpopc(int x) { int c = 0; while (x) { c += x & 1; x >>= 1; } return c; }

struct Tab {
    signed char sgn[16][16];  // sign of gp term including reverse() on j operand; 0 = absent
    signed char oi [16][16];  // output blade index
};

constexpr Tab make_tab() {
    Tab t{};
    int order[16] = {};
    int p = 0;
    for (int g = 0; g <= 4; ++g)
        for (int bm = 0; bm < 16; ++bm)
            if (cpopc(bm) == g) order[p++] = bm;
    int idx[16] = {};
    for (int i = 0; i < 16; ++i) idx[order[i]] = i;

    for (int j = 0; j < 16; ++j) {
        const int a  = order[j];
        const int gj = cpopc(a);
        const int rev = ((gj * (gj - 1) / 2) % 2) ? -1 : 1;   // reverse sign on operand j
        for (int k = 0; k < 16; ++k) {
            const int b = order[k];
            t.sgn[j][k] = 0;
            t.oi [j][k] = 0;
            if (a & b & 1) continue;            // shared e0 factor -> 0
            int s = 0, tt = a >> 1;
            while (tt) { s += cpopc(tt & b); tt >>= 1; }
            const int sign = (s & 1) ? -1 : 1;
            t.sgn[j][k] = (signed char)(sign * rev);
            t.oi [j][k] = (signed char)idx[a ^ b];
        }
    }
    return t;
}
constexpr Tab TAB = make_tab();

// ---------------- f32x2 packed helpers ----------------
__device__ __forceinline__ ull pack2(float x, float y) {
    ull r;
    asm("mov.b64 %0, {%1, %2};" : "=l"(r) : "f"(x), "f"(y));
    return r;
}
__device__ __forceinline__ void unpack2(ull v, float& x, float& y) {
    asm("mov.b64 {%0, %1}, %2;" : "=f"(x), "=f"(y) : "l"(v));
}
__device__ __forceinline__ void ffma2(ull& d, ull a, ull b) {
    asm("fma.rn.f32x2 %0, %1, %2, %0;" : "+l"(d) : "l"(a), "l"(b));
}

// ---------------- fully-unrolled contraction via template recursion ----------
// All TAB accesses use template parameters -> constant expressions -> no LDC,
// no branches: 192 straight-line FFMA2 instructions.
template <int J, int K>
struct Term {
    static __device__ __forceinline__ void run(ull* acc, ull ap, ull an, const ull* t2) {
        constexpr int s = TAB.sgn[J][K];
        constexpr int o = TAB.oi [J][K];
        if constexpr (s > 0) ffma2(acc[o], ap, t2[K]);
        if constexpr (s < 0) ffma2(acc[o], an, t2[K]);
        if constexpr (K < 15) Term<J, K + 1>::run(acc, ap, an, t2);
    }
};

template <int J>
struct JLoop {
    static __device__ __forceinline__ void run(ull* acc, const ull* sP, const ull* sN, const ull* t2) {
        const ull ap = sP[J];
        const ull an = sN[J];
        Term<J, 0>::run(acc, ap, an, t2);
        if constexpr (J < 15) JLoop<J + 1>::run(acc, sP, sN, t2);
    }
};

// ---------------- kernel ----------------
__global__ __launch_bounds__(THREADS)
void grt_pairs_kernel(const float* __restrict__ T, float* __restrict__ out) {
    __shared__ ull sPos[TILE_N][16];
    __shared__ ull sNeg[TILE_N][16];

    const int tid = threadIdx.x;
    const int mt  = blockIdx.x;   // m tile: 0..(NRES/MTILE-1)
    const int nt  = blockIdx.y;   // n tile: 0..(NRES/TILE_N-1)
    const int b   = blockIdx.z;   // batch
    const int nbase = nt * TILE_N;

    // Stage the n-tile rows as packed broadcast pairs (a,a) and (-a,-a).
    {
        const int n = tid >> 4;   // 0..15
        const int j = tid & 15;   // 0..15
        const float a = T[((size_t)b * NRES + (nbase + n)) * NBLADE + j];
        sPos[n][j] = pack2(a, a);
        sNeg[n][j] = pack2(-a, -a);
    }

    // Load this thread's two m rows, pack lane-wise into f32x2.
    const int m0 = mt * MTILE + tid;
    const int m1 = m0 + THREADS;
    ull t2[16];
    {
        const float4* r0 = reinterpret_cast<const float4*>(T + ((size_t)b * NRES + m0) * NBLADE);
        const float4* r1 = reinterpret_cast<const float4*>(T + ((size_t)b * NRES + m1) * NBLADE);
#pragma unroll
        for (int q = 0; q < 4; ++q) {
            const float4 x = r0[q];
            const float4 y = r1[q];
            t2[q * 4 + 0] = pack2(x.x, y.x);
            t2[q * 4 + 1] = pack2(x.y, y.y);
            t2[q * 4 + 2] = pack2(x.z, y.z);
            t2[q * 4 + 3] = pack2(x.w, y.w);
        }
    }
    __syncthreads();

    float* const outb = out + (size_t)b * NRES * NRES * NBLADE;

#pragma unroll 1
    for (int nn = 0; nn < TILE_N; ++nn) {
        ull acc[16];
#pragma unroll
        for (int i = 0; i < 16; ++i) acc[i] = 0ULL;  // packed (+0.0f, +0.0f)

        JLoop<0>::run(acc, &sPos[nn][0], &sNeg[nn][0], t2);

        float ra[16], rb[16];
#pragma unroll
        for (int i = 0; i < 16; ++i) unpack2(acc[i], ra[i], rb[i]);

        const size_t n = (size_t)(nbase + nn);
        float4* o0 = reinterpret_cast<float4*>(outb + (n * NRES + m0) * NBLADE);
        float4* o1 = reinterpret_cast<float4*>(outb + (n * NRES + m1) * NBLADE);
#pragma unroll
        for (int q = 0; q < 4; ++q) {
            __stcs(o0 + q, make_float4(ra[4 * q + 0], ra[4 * q + 1], ra[4 * q + 2], ra[4 * q + 3]));
            __stcs(o1 + q, make_float4(rb[4 * q + 0], rb[4 * q + 1], rb[4 * q + 2], rb[4 * q + 3]));
        }
    }
}

// ---------------- launch ----------------
extern "C" void kernel_launch(void* const* d_in, const int* in_sizes, int n_in,
                              void* d_out, int out_size) {
    const float* T = (const float*)d_in[0];
    float* out = (float*)d_out;
    (void)in_sizes; (void)n_in; (void)out_size;

    dim3 grid(NRES / MTILE, NRES / TILE_N, BATCH);
    grt_pairs_kernel<<<grid, THREADS>>>(T, out);
}